// round 1
// baseline (speedup 1.0000x reference)
#include <cuda_runtime.h>

// RNN: h_t = tanh([x_t, h_{t-1}] @ W_cell + b_cell), then logits = h_T @ W_out + b_out
// B=4096, T=128, D=128, H=150, O=10.
//
// Persistent-CTA design: each CTA owns 32 batch rows for all 128 timesteps.
// W_cell lives in SMEM (loaded once), operands A=[x_t|h] stored transposed
// [k][b] so the inner loop is 2x LDS.128 + 16 FFMA per k (FMA-pipe bound).

#define T_SEQ   128
#define D_IN    128
#define H_HID   150
#define O_OUT   10
#define KDIM    (D_IN + H_HID)   // 278
#define JPAD    160              // H padded so 40 j-groups * 4 = 160
#define B_BLK   32
#define APAD    36               // A row stride (floats), 16B-aligned vec4 at b0%4==0
#define NTHREADS 320             // 8 b-groups (x4 rows) * 40 j-groups (x4 cols)

__global__ void __launch_bounds__(NTHREADS, 1)
rnn_persist_kernel(const float* __restrict__ X,
                   const float* __restrict__ Wc,
                   const float* __restrict__ bc,
                   const float* __restrict__ Wo,
                   const float* __restrict__ bo,
                   float* __restrict__ out)
{
    extern __shared__ float smem[];
    float* Wsh = smem;                                // [KDIM][JPAD]
    float* Ash = Wsh + KDIM * JPAD;                   // [(D_IN+JPAD)][APAD]; rows 0..127 = x_t, 128..277 = h
    float* bsh = Ash + (D_IN + JPAD) * APAD;          // [JPAD]

    const int tid = threadIdx.x;
    const long ctaB0 = (long)blockIdx.x * B_BLK;
    const float* Xb = X + ctaB0 * T_SEQ * D_IN;

    // ---- load W_cell into SMEM, zero-padded to JPAD columns ----
    for (int i = tid; i < KDIM * JPAD; i += NTHREADS) {
        int k = i / JPAD;
        int j = i - k * JPAD;
        Wsh[i] = (j < H_HID) ? Wc[k * H_HID + j] : 0.0f;
    }
    for (int j = tid; j < JPAD; j += NTHREADS)
        bsh[j] = (j < H_HID) ? bc[j] : 0.0f;
    // zero h region (rows 128 .. 128+JPAD-1)
    for (int i = tid; i < JPAD * APAD; i += NTHREADS)
        Ash[D_IN * APAD + i] = 0.0f;

    // ---- load x_0 transposed into A[0..127][b] ----
#pragma unroll
    for (int s = 0; s < 4; s++) {
        int i = tid + s * NTHREADS;
        if (i < B_BLK * (D_IN / 4)) {       // 1024 float4s
            int r = i >> 5;                 // batch row 0..31
            int c = i & 31;                 // float4 column
            float4 v = *(const float4*)&Xb[(long)r * T_SEQ * D_IN + c * 4];
            Ash[(c * 4 + 0) * APAD + r] = v.x;
            Ash[(c * 4 + 1) * APAD + r] = v.y;
            Ash[(c * 4 + 2) * APAD + r] = v.z;
            Ash[(c * 4 + 3) * APAD + r] = v.w;
        }
    }
    __syncthreads();

    const int jg = tid % 40;
    const int bg = tid / 40;
    const int j0 = jg * 4;
    const int b0 = bg * 4;
    const float4 bias = *(const float4*)&bsh[j0];

    for (int t = 0; t < T_SEQ; t++) {
        // prefetch x_{t+1} into registers (hidden behind the k-loop)
        float4 xr[4];
        const bool havex = (t + 1 < T_SEQ);
#pragma unroll
        for (int s = 0; s < 4; s++) {
            int i = tid + s * NTHREADS;
            if (havex && i < B_BLK * (D_IN / 4)) {
                int r = i >> 5;
                int c = i & 31;
                xr[s] = *(const float4*)&Xb[(long)r * T_SEQ * D_IN + (long)(t + 1) * D_IN + c * 4];
            } else {
                xr[s] = make_float4(0.f, 0.f, 0.f, 0.f);
            }
        }

        // ---- main GEMM tile: acc[bb][jj] += A[k][b0+bb] * W[k][j0+jj] ----
        float acc[4][4];
#pragma unroll
        for (int bb = 0; bb < 4; bb++)
#pragma unroll
            for (int jj = 0; jj < 4; jj++)
                acc[bb][jj] = 0.0f;

#pragma unroll 2
        for (int k = 0; k < KDIM; k++) {
            float4 wv = *(const float4*)&Wsh[k * JPAD + j0];
            float4 av = *(const float4*)&Ash[k * APAD + b0];
            acc[0][0] += av.x * wv.x; acc[0][1] += av.x * wv.y;
            acc[0][2] += av.x * wv.z; acc[0][3] += av.x * wv.w;
            acc[1][0] += av.y * wv.x; acc[1][1] += av.y * wv.y;
            acc[1][2] += av.y * wv.z; acc[1][3] += av.y * wv.w;
            acc[2][0] += av.z * wv.x; acc[2][1] += av.z * wv.y;
            acc[2][2] += av.z * wv.z; acc[2][3] += av.z * wv.w;
            acc[3][0] += av.w * wv.x; acc[3][1] += av.w * wv.y;
            acc[3][2] += av.w * wv.z; acc[3][3] += av.w * wv.w;
        }

        __syncthreads();   // all reads of A (x and h) done

        // write h_new = tanh(acc + bias), vectorized over batch (contiguous in A)
        {
            float4 h;
            h.x = tanhf(acc[0][0] + bias.x); h.y = tanhf(acc[1][0] + bias.x);
            h.z = tanhf(acc[2][0] + bias.x); h.w = tanhf(acc[3][0] + bias.x);
            *(float4*)&Ash[(D_IN + j0 + 0) * APAD + b0] = h;
            h.x = tanhf(acc[0][1] + bias.y); h.y = tanhf(acc[1][1] + bias.y);
            h.z = tanhf(acc[2][1] + bias.y); h.w = tanhf(acc[3][1] + bias.y);
            *(float4*)&Ash[(D_IN + j0 + 1) * APAD + b0] = h;
            h.x = tanhf(acc[0][2] + bias.z); h.y = tanhf(acc[1][2] + bias.z);
            h.z = tanhf(acc[2][2] + bias.z); h.w = tanhf(acc[3][2] + bias.z);
            *(float4*)&Ash[(D_IN + j0 + 2) * APAD + b0] = h;
            h.x = tanhf(acc[0][3] + bias.w); h.y = tanhf(acc[1][3] + bias.w);
            h.z = tanhf(acc[2][3] + bias.w); h.w = tanhf(acc[3][3] + bias.w);
            *(float4*)&Ash[(D_IN + j0 + 3) * APAD + b0] = h;
        }

        // store prefetched x_{t+1} transposed into A
        if (havex) {
#pragma unroll
            for (int s = 0; s < 4; s++) {
                int i = tid + s * NTHREADS;
                if (i < B_BLK * (D_IN / 4)) {
                    int r = i >> 5;
                    int c = i & 31;
                    Ash[(c * 4 + 0) * APAD + r] = xr[s].x;
                    Ash[(c * 4 + 1) * APAD + r] = xr[s].y;
                    Ash[(c * 4 + 2) * APAD + r] = xr[s].z;
                    Ash[(c * 4 + 3) * APAD + r] = xr[s].w;
                }
            }
        }
        __syncthreads();   // h_new + x_{t+1} visible before next step reads
    }

    // ---- classifier head: out[b][o] = h_T[b] . W_out[:,o] + b_out[o] ----
    // 320 threads == 32 batch rows * 10 outputs, exact.
    {
        const int b = tid / O_OUT;
        const int o = tid - b * O_OUT;
        float s = bo[o];
#pragma unroll 5
        for (int j = 0; j < H_HID; j++)
            s += Ash[(D_IN + j) * APAD + b] * Wo[j * O_OUT + o];
        out[(ctaB0 + b) * O_OUT + o] = s;
    }
}

extern "C" void kernel_launch(void* const* d_in, const int* in_sizes, int n_in,
                              void* d_out, int out_size)
{
    const float* X  = (const float*)d_in[0];  // [B, T, D]
    const float* Wc = (const float*)d_in[1];  // [D+H, H]
    const float* bc = (const float*)d_in[2];  // [H]
    const float* Wo = (const float*)d_in[3];  // [H, O]
    const float* bo = (const float*)d_in[4];  // [O]
    float* out = (float*)d_out;               // [B, O]

    const int B = in_sizes[0] / (T_SEQ * D_IN);   // 4096
    const size_t smem_bytes =
        (size_t)(KDIM * JPAD + (D_IN + JPAD) * APAD + JPAD) * sizeof(float);  // ~220 KB

    cudaFuncSetAttribute(rnn_persist_kernel,
                         cudaFuncAttributeMaxDynamicSharedMemorySize,
                         (int)smem_bytes);

    rnn_persist_kernel<<<B / B_BLK, NTHREADS, smem_bytes>>>(X, Wc, bc, Wo, bo, out);
}